// round 2
// baseline (speedup 1.0000x reference)
#include <cuda_runtime.h>
#include <math.h>

#define BATCH 8192
#define NB    11      // GRID_SIZE + SPLINE_ORDER
#define PERF  12      // 1 gelu + 11 spline bases per input feature
#define BN_EPS 1e-5f

// ---------------- scratch (static device globals; no runtime allocation) ----
static __device__ float g_E[50331648];   // 8192 * 6144 max expanded activations
static __device__ float g_h[BATCH * 512]; // hidden activations
static __device__ float g_Wp[6144 * 512]; // packed weights [K, N]

// ---------------- weight packing: Wp[k=i*12+j][n] ---------------------------
__global__ void pack_w_kernel(const float* __restrict__ base_w,
                              const float* __restrict__ spline_w,
                              int IN, int N)
{
    int idx = blockIdx.x * blockDim.x + threadIdx.x;
    int K = IN * PERF;
    if (idx >= K * N) return;
    int k = idx / N;
    int n = idx - k * N;
    int i = k / PERF;
    int j = k - i * PERF;
    float v;
    if (j == 0) v = base_w[(size_t)n * IN + i];
    else        v = spline_w[((size_t)n * IN + i) * NB + (j - 1)];
    g_Wp[idx] = v;
}

// ---------------- activation expansion: E[b][i*12 + {gelu, B0..B10}] --------
__global__ void expand_kernel(const float* __restrict__ xin,
                              const float* __restrict__ grid,
                              int IN)
{
    int idx = blockIdx.x * blockDim.x + threadIdx.x;
    if (idx >= BATCH * IN) return;
    int b = idx / IN;
    int i = idx - b * IN;

    float xv = xin[(size_t)b * IN + i];

    float gg[15];
#pragma unroll
    for (int j = 0; j < 15; j++) gg[j] = grid[i * 15 + j];

    float bas[14];
#pragma unroll
    for (int j = 0; j < 14; j++)
        bas[j] = (xv >= gg[j] && xv < gg[j + 1]) ? 1.0f : 0.0f;

#pragma unroll
    for (int k = 1; k <= 3; k++) {
#pragma unroll
        for (int j = 0; j < 14 - 1; j++) {
            if (j < 14 - k) {
                float left  = (xv - gg[j]) / (gg[j + k] - gg[j]);
                float right = (gg[j + k + 1] - xv) / (gg[j + k + 1] - gg[j + 1]);
                bas[j] = left * bas[j] + right * bas[j + 1];
            }
        }
    }

    size_t base = (size_t)b * IN * PERF + (size_t)i * PERF;
    // exact GELU (approximate=False): 0.5*x*(1+erf(x/sqrt(2)))
    g_E[base] = 0.5f * xv * (1.0f + erff(xv * 0.70710678118654752f));
#pragma unroll
    for (int j = 0; j < NB; j++) g_E[base + 1 + j] = bas[j];
}

// ---------------- fp32 SGEMM: C[M,N] = E[M,K] * Wp[K,N], optional BN --------
__global__ void __launch_bounds__(256)
sgemm_kernel(float* __restrict__ C, int M, int N, int K, int do_bn,
             const float* __restrict__ gamma, const float* __restrict__ beta,
             const float* __restrict__ mean,  const float* __restrict__ var)
{
    __shared__ float As[8][132];   // padded to avoid bank conflicts
    __shared__ float Bs[8][128];

    int tid = threadIdx.x;
    int tx = tid & 15;
    int ty = tid >> 4;
    int bm = blockIdx.y * 128;
    int bn = blockIdx.x * 128;

    float acc[8][8];
#pragma unroll
    for (int r = 0; r < 8; r++)
#pragma unroll
        for (int c = 0; c < 8; c++) acc[r][c] = 0.0f;

    for (int k0 = 0; k0 < K; k0 += 8) {
#pragma unroll
        for (int it = 0; it < 4; it++) {
            int e = tid + 256 * it;
            int m = e >> 3, k = e & 7;
            As[k][m] = g_E[(size_t)(bm + m) * K + k0 + k];
        }
#pragma unroll
        for (int it = 0; it < 4; it++) {
            int e = tid + 256 * it;
            int k = e >> 7, n = e & 127;
            Bs[k][n] = g_Wp[(size_t)(k0 + k) * N + bn + n];
        }
        __syncthreads();

#pragma unroll
        for (int kk = 0; kk < 8; kk++) {
            float a[8], bb[8];
#pragma unroll
            for (int r = 0; r < 8; r++) a[r] = As[kk][ty + 16 * r];
#pragma unroll
            for (int c = 0; c < 8; c++) bb[c] = Bs[kk][tx + 16 * c];
#pragma unroll
            for (int r = 0; r < 8; r++)
#pragma unroll
                for (int c = 0; c < 8; c++)
                    acc[r][c] = fmaf(a[r], bb[c], acc[r][c]);
        }
        __syncthreads();
    }

#pragma unroll
    for (int r = 0; r < 8; r++) {
        int row = bm + ty + 16 * r;
#pragma unroll
        for (int c = 0; c < 8; c++) {
            int col = bn + tx + 16 * c;
            float v = acc[r][c];
            if (do_bn)
                v = gamma[col] * (v - mean[col]) * rsqrtf(var[col] + BN_EPS) + beta[col];
            C[(size_t)row * N + col] = v;
        }
    }
}

// ---------------- launch -----------------------------------------------------
extern "C" void kernel_launch(void* const* d_in, const int* in_sizes, int n_in,
                              void* d_out, int out_size)
{
    (void)in_sizes; (void)n_in; (void)out_size;
    const float* x         = (const float*)d_in[0];
    const float* grid0     = (const float*)d_in[1];
    const float* base_w0   = (const float*)d_in[2];
    const float* spline_w0 = (const float*)d_in[3];
    const float* grid1     = (const float*)d_in[4];
    const float* base_w1   = (const float*)d_in[5];
    const float* spline_w1 = (const float*)d_in[6];
    const float* grid2     = (const float*)d_in[7];
    const float* base_w2   = (const float*)d_in[8];
    const float* spline_w2 = (const float*)d_in[9];
    const float* bn_gamma  = (const float*)d_in[10];
    const float* bn_beta   = (const float*)d_in[11];
    const float* bn_mean   = (const float*)d_in[12];
    const float* bn_var    = (const float*)d_in[13];
    float* out = (float*)d_out;

    float* hptr = nullptr;
    cudaGetSymbolAddress((void**)&hptr, g_h);

    const int TB = 256;

    // ---- layer 0: 256 -> 512 ----
    {
        int IN = 256, N = 512, K = IN * PERF; // 3072
        pack_w_kernel<<<(K * N + TB - 1) / TB, TB>>>(base_w0, spline_w0, IN, N);
        expand_kernel<<<(BATCH * IN + TB - 1) / TB, TB>>>(x, grid0, IN);
        dim3 g(N / 128, BATCH / 128);
        sgemm_kernel<<<g, 256>>>(hptr, BATCH, N, K, 0, nullptr, nullptr, nullptr, nullptr);
    }
    // ---- layer 1: 512 -> 512 ----
    {
        int IN = 512, N = 512, K = IN * PERF; // 6144
        pack_w_kernel<<<(K * N + TB - 1) / TB, TB>>>(base_w1, spline_w1, IN, N);
        expand_kernel<<<(BATCH * IN + TB - 1) / TB, TB>>>(hptr, grid1, IN);
        dim3 g(N / 128, BATCH / 128);
        sgemm_kernel<<<g, 256>>>(hptr, BATCH, N, K, 0, nullptr, nullptr, nullptr, nullptr);
    }
    // ---- layer 2: 512 -> 256, fused BatchNorm ----
    {
        int IN = 512, N = 256, K = IN * PERF; // 6144
        pack_w_kernel<<<(K * N + TB - 1) / TB, TB>>>(base_w2, spline_w2, IN, N);
        expand_kernel<<<(BATCH * IN + TB - 1) / TB, TB>>>(hptr, grid2, IN);
        dim3 g(N / 128, BATCH / 128);
        sgemm_kernel<<<g, 256>>>(out, BATCH, N, K, 1, bn_gamma, bn_beta, bn_mean, bn_var);
    }
}

// round 4
// speedup vs baseline: 3.4849x; 3.4849x over previous
#include <cuda_runtime.h>
#include <cuda_bf16.h>
#include <math.h>
#include <stdint.h>

#define BATCH 8192
#define NB    11
#define PERF  12
#define BN_EPS 1e-5f

// ---------------- static scratch (no runtime allocation) --------------------
static __device__ __align__(128) __nv_bfloat16 g_Eh[BATCH * 6144];
static __device__ __align__(128) __nv_bfloat16 g_El[BATCH * 6144];
static __device__ __align__(128) __nv_bfloat16 g_Wh[6144 * 512];
static __device__ __align__(128) __nv_bfloat16 g_Wl[6144 * 512];
static __device__ float g_h[BATCH * 512];

// ---------------- PTX helpers (family-target safe: sm_80+ ISA only) ---------
__device__ __forceinline__ uint32_t smem_u32(const void* p) {
    uint32_t a;
    asm("{ .reg .u64 t; cvta.to.shared.u64 t, %1; cvt.u32.u64 %0, t; }" : "=r"(a) : "l"(p));
    return a;
}
__device__ __forceinline__ void ldsm4(uint32_t* r, uint32_t addr) {
    asm volatile("ldmatrix.sync.aligned.m8n8.x4.shared.b16 {%0,%1,%2,%3}, [%4];"
                 : "=r"(r[0]), "=r"(r[1]), "=r"(r[2]), "=r"(r[3]) : "r"(addr));
}
__device__ __forceinline__ void mma16816(float* d, const uint32_t* a, const uint32_t* b) {
    asm volatile("mma.sync.aligned.m16n8k16.row.col.f32.bf16.bf16.f32 "
                 "{%0,%1,%2,%3}, {%4,%5,%6,%7}, {%8,%9}, {%0,%1,%2,%3};"
                 : "+f"(d[0]), "+f"(d[1]), "+f"(d[2]), "+f"(d[3])
                 : "r"(a[0]), "r"(a[1]), "r"(a[2]), "r"(a[3]), "r"(b[0]), "r"(b[1]));
}
__device__ __forceinline__ void cp16(uint32_t dst, const void* src) {
    asm volatile("cp.async.cg.shared.global [%0], [%1], 16;" :: "r"(dst), "l"(src));
}
__device__ __forceinline__ void cp_commit() {
    asm volatile("cp.async.commit_group;" ::: "memory");
}
template <int W> __device__ __forceinline__ void cp_wait() {
    asm volatile("cp.async.wait_group %0;" :: "n"(W) : "memory");
}

// ---------------- weight pack: Wh/Wl[n][k], k = i*12 + j --------------------
__global__ void pack_w_kernel(const float* __restrict__ base_w,
                              const float* __restrict__ spline_w,
                              int IN, int N)
{
    int idx = blockIdx.x * blockDim.x + threadIdx.x;
    int K = IN * PERF;
    if (idx >= N * K) return;
    int n = idx / K;
    int k = idx - n * K;
    int i = k / PERF;
    int j = k - i * PERF;
    float v;
    if (j == 0) v = base_w[(size_t)n * IN + i];
    else        v = spline_w[((size_t)n * IN + i) * NB + (j - 1)];
    __nv_bfloat16 hi = __float2bfloat16(v);
    float lo = v - __bfloat162float(hi);
    g_Wh[idx] = hi;
    g_Wl[idx] = __float2bfloat16(lo);
}

// ---------------- expansion: Eh/El[b][i*12 + {gelu, B0..B10}] ---------------
__global__ void expand_kernel(const float* __restrict__ xin,
                              const float* __restrict__ grid,
                              int IN)
{
    int idx = blockIdx.x * blockDim.x + threadIdx.x;
    if (idx >= BATCH * IN) return;
    int b = idx / IN;
    int i = idx - b * IN;

    float xv = xin[(size_t)b * IN + i];

    float gg[15];
#pragma unroll
    for (int j = 0; j < 15; j++) gg[j] = grid[i * 15 + j];

    float bas[14];
#pragma unroll
    for (int j = 0; j < 14; j++)
        bas[j] = (xv >= gg[j] && xv < gg[j + 1]) ? 1.0f : 0.0f;

#pragma unroll
    for (int k = 1; k <= 3; k++) {
#pragma unroll
        for (int j = 0; j < 13; j++) {
            if (j < 14 - k) {
                float left  = (xv - gg[j]) / (gg[j + k] - gg[j]);
                float right = (gg[j + k + 1] - xv) / (gg[j + k + 1] - gg[j + 1]);
                bas[j] = left * bas[j] + right * bas[j + 1];
            }
        }
    }

    float vals[PERF];
    vals[0] = 0.5f * xv * (1.0f + erff(xv * 0.70710678118654752f));
#pragma unroll
    for (int j = 0; j < NB; j++) vals[1 + j] = bas[j];

    size_t base = (size_t)b * IN * PERF + (size_t)i * PERF;
#pragma unroll
    for (int j = 0; j < PERF; j++) {
        __nv_bfloat16 hi = __float2bfloat16(vals[j]);
        float lo = vals[j] - __bfloat162float(hi);
        g_Eh[base + j] = hi;
        g_El[base + j] = __float2bfloat16(lo);
    }
}

// ---------------- HMMA GEMM: C[M,N] = E[M,K] * W[K,N] (3-term hi/lo) --------
// CTA tile 128x128, warp tile 32x64 (4x2 warps), K-chunk 64, cp.async 2-stage.
// SMEM per buffer: Ah|Al|Bh|Bl, each 128x64 bf16 = 16KB. Two buffers = 128KB.
#define TILE_B   16384
#define BUF_B    (4 * TILE_B)
#define SMEM_TOT (2 * BUF_B)

__global__ void __launch_bounds__(256, 1)
kan_gemm(float* __restrict__ C,
         const __nv_bfloat16* __restrict__ Eh, const __nv_bfloat16* __restrict__ El,
         const __nv_bfloat16* __restrict__ Wh, const __nv_bfloat16* __restrict__ Wl,
         int N, int Kd, int NC, int do_bn,
         const float* __restrict__ gamma, const float* __restrict__ beta,
         const float* __restrict__ mean,  const float* __restrict__ var)
{
    extern __shared__ __align__(128) char smem[];
    const uint32_t sbase = smem_u32(smem);

    const int tid  = threadIdx.x;
    const int wid  = tid >> 5;
    const int lane = tid & 31;
    const int bm = blockIdx.y * 128, bn = blockIdx.x * 128;

    const int warp_m = wid & 3, warp_n = wid >> 2;
    const int m_base = warp_m * 32, n_base = warp_n * 64;

    const __nv_bfloat16* srcs[4] = {Eh, El, Wh, Wl};

    // per-thread load geometry: 4 iters x (row = tid>>3 + 32*it, 16B col tid&7)
    const int lr0 = tid >> 3;
    const int lc  = tid & 7;
    uint32_t so_base[4];
#pragma unroll
    for (int it = 0; it < 4; it++) {
        uint32_t so = (uint32_t)((lr0 + 32 * it) * 128 + lc * 16);
        so_base[it] = so ^ ((so >> 3) & 0x70);
    }

    // chunk loader
    auto load_chunk = [&](int c) {
        int k0 = c * 64;
        uint32_t bufo = (uint32_t)(c & 1) * BUF_B;
#pragma unroll
        for (int arr = 0; arr < 4; arr++) {
            const __nv_bfloat16* p = srcs[arr];
            int rbase = (arr < 2) ? bm : bn;
            uint32_t dst0 = sbase + bufo + (uint32_t)arr * TILE_B;
#pragma unroll
            for (int it = 0; it < 4; it++) {
                int r = lr0 + 32 * it;
                cp16(dst0 + so_base[it],
                     p + (size_t)(rbase + r) * Kd + k0 + lc * 8);
            }
        }
        cp_commit();
    };

    float acc[2][8][4];
#pragma unroll
    for (int mt = 0; mt < 2; mt++)
#pragma unroll
        for (int nt = 0; nt < 8; nt++)
#pragma unroll
            for (int e = 0; e < 4; e++) acc[mt][nt][e] = 0.0f;

    // precompute swizzled ldmatrix offsets (per k16 they shift by 32B pre-swizzle)
    // A: row = m_base + mt*16 + (lane&7) + ((lane>>3)&1)*8 ; kbyte = (lane>>4)*16
    // B: row = n_base + ng*16 + (lane&7) + (lane>>4)*8     ; kbyte = ((lane>>3)&1)*16
    int a_row[2], b_row[4];
#pragma unroll
    for (int mt = 0; mt < 2; mt++)
        a_row[mt] = m_base + mt * 16 + (lane & 7) + ((lane >> 3) & 1) * 8;
#pragma unroll
    for (int ng = 0; ng < 4; ng++)
        b_row[ng] = n_base + ng * 16 + (lane & 7) + (lane >> 4) * 8;
    const int a_kb = (lane >> 4) * 16;
    const int b_kb = ((lane >> 3) & 1) * 16;

    load_chunk(0);

    for (int c = 0; c < NC; c++) {
        if (c + 1 < NC) { load_chunk(c + 1); cp_wait<1>(); }
        else             cp_wait<0>();
        __syncthreads();

        uint32_t bufo = (uint32_t)(c & 1) * BUF_B;
        uint32_t sAh = sbase + bufo;
        uint32_t sAl = sAh + TILE_B;
        uint32_t sBh = sAh + 2 * TILE_B;
        uint32_t sBl = sAh + 3 * TILE_B;

#pragma unroll
        for (int k16 = 0; k16 < 4; k16++) {
            int kb = k16 * 32;
            uint32_t ah[2][4], al[2][4], bh[8][2], bl[8][2];
#pragma unroll
            for (int mt = 0; mt < 2; mt++) {
                uint32_t off = (uint32_t)(a_row[mt] * 128 + kb + a_kb);
                off ^= (off >> 3) & 0x70;
                ldsm4(ah[mt], sAh + off);
                ldsm4(al[mt], sAl + off);
            }
#pragma unroll
            for (int ng = 0; ng < 4; ng++) {
                uint32_t off = (uint32_t)(b_row[ng] * 128 + kb + b_kb);
                off ^= (off >> 3) & 0x70;
                uint32_t t[4];
                ldsm4(t, sBh + off);
                bh[ng * 2][0] = t[0]; bh[ng * 2][1] = t[1];
                bh[ng * 2 + 1][0] = t[2]; bh[ng * 2 + 1][1] = t[3];
                ldsm4(t, sBl + off);
                bl[ng * 2][0] = t[0]; bl[ng * 2][1] = t[1];
                bl[ng * 2 + 1][0] = t[2]; bl[ng * 2 + 1][1] = t[3];
            }
#pragma unroll
            for (int mt = 0; mt < 2; mt++)
#pragma unroll
                for (int nt = 0; nt < 8; nt++) {
                    mma16816(acc[mt][nt], ah[mt], bh[nt]);
                    mma16816(acc[mt][nt], ah[mt], bl[nt]);
                    mma16816(acc[mt][nt], al[mt], bh[nt]);
                }
        }
        __syncthreads();
    }

    // epilogue: fragments -> gmem (float2 stores), optional fused BN
    const int g  = lane >> 2;
    const int tq = lane & 3;
#pragma unroll
    for (int mt = 0; mt < 2; mt++) {
        int row0 = bm + m_base + mt * 16 + g;
#pragma unroll
        for (int nt = 0; nt < 8; nt++) {
            int col = bn + n_base + nt * 8 + tq * 2;
            float v0 = acc[mt][nt][0], v1 = acc[mt][nt][1];
            float v2 = acc[mt][nt][2], v3 = acc[mt][nt][3];
            if (do_bn) {
                float s0 = gamma[col]     * rsqrtf(var[col]     + BN_EPS);
                float s1 = gamma[col + 1] * rsqrtf(var[col + 1] + BN_EPS);
                float m0 = mean[col], m1 = mean[col + 1];
                float b0 = beta[col], b1 = beta[col + 1];
                v0 = s0 * (v0 - m0) + b0;  v1 = s1 * (v1 - m1) + b1;
                v2 = s0 * (v2 - m0) + b0;  v3 = s1 * (v3 - m1) + b1;
            }
            *(float2*)&C[(size_t)row0 * N + col]       = make_float2(v0, v1);
            *(float2*)&C[(size_t)(row0 + 8) * N + col] = make_float2(v2, v3);
        }
    }
}

// ---------------- launch -----------------------------------------------------
extern "C" void kernel_launch(void* const* d_in, const int* in_sizes, int n_in,
                              void* d_out, int out_size)
{
    (void)in_sizes; (void)n_in; (void)out_size;
    const float* x         = (const float*)d_in[0];
    const float* grid0     = (const float*)d_in[1];
    const float* base_w0   = (const float*)d_in[2];
    const float* spline_w0 = (const float*)d_in[3];
    const float* grid1     = (const float*)d_in[4];
    const float* base_w1   = (const float*)d_in[5];
    const float* spline_w1 = (const float*)d_in[6];
    const float* grid2     = (const float*)d_in[7];
    const float* base_w2   = (const float*)d_in[8];
    const float* spline_w2 = (const float*)d_in[9];
    const float* bn_gamma  = (const float*)d_in[10];
    const float* bn_beta   = (const float*)d_in[11];
    const float* bn_mean   = (const float*)d_in[12];
    const float* bn_var    = (const float*)d_in[13];
    float* out = (float*)d_out;

    float* hptr = nullptr;
    cudaGetSymbolAddress((void**)&hptr, g_h);
    __nv_bfloat16 *eh = nullptr, *el = nullptr, *wh = nullptr, *wl = nullptr;
    cudaGetSymbolAddress((void**)&eh, g_Eh);
    cudaGetSymbolAddress((void**)&el, g_El);
    cudaGetSymbolAddress((void**)&wh, g_Wh);
    cudaGetSymbolAddress((void**)&wl, g_Wl);

    cudaFuncSetAttribute(kan_gemm, cudaFuncAttributeMaxDynamicSharedMemorySize, SMEM_TOT);

    const int TB = 256;

    // ---- layer 0: 256 -> 512 ----
    {
        int IN = 256, N = 512, K = IN * PERF;   // 3072
        pack_w_kernel<<<(N * K + TB - 1) / TB, TB>>>(base_w0, spline_w0, IN, N);
        expand_kernel<<<(BATCH * IN + TB - 1) / TB, TB>>>(x, grid0, IN);
        dim3 g(N / 128, BATCH / 128);
        kan_gemm<<<g, 256, SMEM_TOT>>>(hptr, eh, el, wh, wl, N, K, K / 64, 0,
                                       nullptr, nullptr, nullptr, nullptr);
    }
    // ---- layer 1: 512 -> 512 ----
    {
        int IN = 512, N = 512, K = IN * PERF;   // 6144
        pack_w_kernel<<<(N * K + TB - 1) / TB, TB>>>(base_w1, spline_w1, IN, N);
        expand_kernel<<<(BATCH * IN + TB - 1) / TB, TB>>>(hptr, grid1, IN);
        dim3 g(N / 128, BATCH / 128);
        kan_gemm<<<g, 256, SMEM_TOT>>>(hptr, eh, el, wh, wl, N, K, K / 64, 0,
                                       nullptr, nullptr, nullptr, nullptr);
    }
    // ---- layer 2: 512 -> 256, fused BatchNorm ----
    {
        int IN = 512, N = 256, K = IN * PERF;   // 6144
        pack_w_kernel<<<(N * K + TB - 1) / TB, TB>>>(base_w2, spline_w2, IN, N);
        expand_kernel<<<(BATCH * IN + TB - 1) / TB, TB>>>(hptr, grid2, IN);
        dim3 g(N / 128, BATCH / 128);
        kan_gemm<<<g, 256, SMEM_TOT>>>(out, eh, el, wh, wl, N, K, K / 64, 1,
                                       bn_gamma, bn_beta, bn_mean, bn_var);
    }
}